// round 16
// baseline (speedup 1.0000x reference)
#include <cuda_runtime.h>
#include <cuda_bf16.h>
#include <cuda_fp16.h>
#include <math.h>
#include <stdint.h>

#define N_NODES 50000
#define E_EDGES 800000
#define ETOT (E_EDGES + N_NODES)
#define CH 128
#define NEG_SLOPE 0.2f
#define BN_EPS 1e-5f
#define PADK 136   // bf16 per smem row (272B) -> conflict-free ldmatrix phases

// ---------------- scratch (static device globals; no allocations) -------------
__device__ __align__(16) __half g_xlh[(size_t)N_NODES * CH];   // fp16 gather payload
__device__ __align__(16) float g_xr[(size_t)N_NODES * CH];
__device__ __align__(16) float g_pre[(size_t)N_NODES * CH];
// fragment-major packed weights: [group g=nc/8 (32)][ks (8)][lane (32)] -> uint2
__device__ __align__(16) uint2 g_wph[32 * 8 * 32];
__device__ __align__(16) uint2 g_wpl[32 * 8 * 32];
__device__ int   g_deg[N_NODES];
__device__ int   g_cur[N_NODES];      // cursor; initialized to exclusive offset
__device__ int   g_offs[N_NODES + 1];
__device__ int   g_src[ETOT];
__device__ int   g_part[64];
__device__ float g_sum[CH];
__device__ float g_sumsq[CH];
__device__ int   g_shift;   // 0: edge_index int32; 1: int64 (read low word)

// ---------------- init (+ dtype detect in block 0) ------------------------------
__global__ void init_k(const int* __restrict__ ei32) {
    int i = blockIdx.x * blockDim.x + threadIdx.x;
    if (i < N_NODES) g_deg[i] = 1;     // self-loop pre-seeded
    if (i < CH) { g_sum[i] = 0.f; g_sumsq[i] = 0.f; }
    if (blockIdx.x == 0) {
        __shared__ int nz;
        if (threadIdx.x == 0) nz = 0;
        __syncthreads();
        if (ei32[2 * threadIdx.x + 1] != 0) atomicOr(&nz, 1);
        __syncthreads();
        if (threadIdx.x == 0) g_shift = nz ? 0 : 1;
    }
}

// ---------------- pack W into B-fragment-major hi/lo layout ----------------------
__global__ void pack_w_k(const float* __restrict__ Wl, const float* __restrict__ Wr) {
    int idx = blockIdx.x * blockDim.x + threadIdx.x;
    if (idx >= 8192) return;
    int lane = idx & 31, ks = (idx >> 5) & 7, g = idx >> 8;
    int nc = g * 8 + (lane >> 2);
    int k0 = ks * 16 + (lane & 3) * 2;
    const float* W = (nc < 128) ? (Wl + nc) : (Wr + nc - 128);
    float w0 = W[(size_t)k0 * 128];
    float w1 = W[(size_t)(k0 + 1) * 128];
    float w2 = W[(size_t)(k0 + 8) * 128];
    float w3 = W[(size_t)(k0 + 9) * 128];
    __nv_bfloat16 h0 = __float2bfloat16(w0), h1 = __float2bfloat16(w1);
    __nv_bfloat16 h2 = __float2bfloat16(w2), h3 = __float2bfloat16(w3);
    __nv_bfloat162 ph0 = __halves2bfloat162(h0, h1), ph1 = __halves2bfloat162(h2, h3);
    __nv_bfloat162 pl0 = __halves2bfloat162(__float2bfloat16(w0 - __bfloat162float(h0)),
                                            __float2bfloat16(w1 - __bfloat162float(h1)));
    __nv_bfloat162 pl1 = __halves2bfloat162(__float2bfloat16(w2 - __bfloat162float(h2)),
                                            __float2bfloat16(w3 - __bfloat162float(h3)));
    g_wph[idx] = make_uint2(*(uint32_t*)&ph0, *(uint32_t*)&ph1);
    g_wpl[idx] = make_uint2(*(uint32_t*)&pl0, *(uint32_t*)&pl1);
}

// ---------------- mma / ldmatrix wrappers ----------------------------------------
__device__ __forceinline__ void mma16816(float* c, const uint32_t* a, const uint32_t* b) {
    asm volatile(
        "mma.sync.aligned.m16n8k16.row.col.f32.bf16.bf16.f32 "
        "{%0,%1,%2,%3}, {%4,%5,%6,%7}, {%8,%9}, {%0,%1,%2,%3};"
        : "+f"(c[0]), "+f"(c[1]), "+f"(c[2]), "+f"(c[3])
        : "r"(a[0]), "r"(a[1]), "r"(a[2]), "r"(a[3]), "r"(b[0]), "r"(b[1]));
}
__device__ __forceinline__ uint32_t smem_u32(const void* p) {
    uint32_t a;
    asm("{ .reg .u64 t; cvta.to.shared.u64 t, %1; cvt.u32.u64 %0, t; }" : "=r"(a) : "l"(p));
    return a;
}
#define LDMX4(r0, r1, r2, r3, a) \
    asm volatile("ldmatrix.sync.aligned.m8n8.x4.shared.b16 {%0,%1,%2,%3}, [%4];" \
        : "=r"(r0), "=r"(r1), "=r"(r2), "=r"(r3) : "r"(a))

// ---------------- tensor-core GEMM: A in smem (ldmatrix), B from packed gmem -----
__global__ void __launch_bounds__(256, 3) gemm_mma_k(const float* __restrict__ x, int n) {
    extern __shared__ __nv_bfloat16 sm[];
    __nv_bfloat16* sAh = sm;                     //  64 x PADK
    __nv_bfloat16* sAl = sAh + 64 * PADK;        //  64 x PADK

    int t = threadIdx.x;
    int row0 = blockIdx.x * 64;
    int by = blockIdx.y;

    for (int l = t; l < 2048; l += 256) {
        int r = l >> 5, j = l & 31;
        float4 v = make_float4(0.f, 0.f, 0.f, 0.f);
        if (row0 + r < n) v = ((const float4*)x)[(size_t)(row0 + r) * 32 + j];
        __nv_bfloat16 h0 = __float2bfloat16(v.x), h1 = __float2bfloat16(v.y);
        __nv_bfloat16 h2 = __float2bfloat16(v.z), h3 = __float2bfloat16(v.w);
        __nv_bfloat162 hA = __halves2bfloat162(h0, h1), hB = __halves2bfloat162(h2, h3);
        __nv_bfloat162 lA = __halves2bfloat162(__float2bfloat16(v.x - __bfloat162float(h0)),
                                               __float2bfloat16(v.y - __bfloat162float(h1)));
        __nv_bfloat162 lB = __halves2bfloat162(__float2bfloat16(v.z - __bfloat162float(h2)),
                                               __float2bfloat16(v.w - __bfloat162float(h3)));
        *(uint2*)&sAh[r * PADK + j * 4] = make_uint2(*(uint32_t*)&hA, *(uint32_t*)&hB);
        *(uint2*)&sAl[r * PADK + j * 4] = make_uint2(*(uint32_t*)&lA, *(uint32_t*)&lB);
    }
    __syncthreads();

    int warp = t >> 5, lane = t & 31;
    int rg = warp >> 2, cg = warp & 3;
    int lr = lane >> 2, lk = (lane & 3) * 2;

    uint32_t aRow = (uint32_t)(rg * 32 + (lane & 15));
    uint32_t aKof = (uint32_t)((lane >> 4) << 3);
    uint32_t aOff = (aRow * PADK + aKof) * 2;
    uint32_t ah_base = smem_u32(sAh) + aOff;
    uint32_t al_base = smem_u32(sAl) + aOff;
    const uint32_t MF_STEP = 16 * PADK * 2;

    int bbase = (by * 16 + cg * 4) * 256 + lane;

    float acc[2][4][4];
    #pragma unroll
    for (int mf = 0; mf < 2; mf++)
        #pragma unroll
        for (int nf = 0; nf < 4; nf++)
            #pragma unroll
            for (int q = 0; q < 4; q++) acc[mf][nf][q] = 0.f;

    #pragma unroll
    for (int ks = 0; ks < 8; ks++) {
        uint32_t ko = (uint32_t)ks * 32;
        uint32_t ah[2][4], al[2][4];
        LDMX4(ah[0][0], ah[0][1], ah[0][2], ah[0][3], ah_base + ko);
        LDMX4(ah[1][0], ah[1][1], ah[1][2], ah[1][3], ah_base + MF_STEP + ko);
        LDMX4(al[0][0], al[0][1], al[0][2], al[0][3], al_base + ko);
        LDMX4(al[1][0], al[1][1], al[1][2], al[1][3], al_base + MF_STEP + ko);
        #pragma unroll
        for (int nf = 0; nf < 4; nf++) {
            uint2 bh = g_wph[bbase + nf * 256 + ks * 32];
            uint2 bl = g_wpl[bbase + nf * 256 + ks * 32];
            uint32_t bhv[2] = {bh.x, bh.y};
            uint32_t blv[2] = {bl.x, bl.y};
            #pragma unroll
            for (int mf = 0; mf < 2; mf++) {
                mma16816(acc[mf][nf], ah[mf], bhv);
                mma16816(acc[mf][nf], ah[mf], blv);
                mma16816(acc[mf][nf], al[mf], bhv);
            }
        }
    }

    #pragma unroll
    for (int mf = 0; mf < 2; mf++) {
        int row = row0 + rg * 32 + mf * 16 + lr;
        #pragma unroll
        for (int nf = 0; nf < 4; nf++) {
            int col = cg * 32 + nf * 8 + lk;
            if (by == 0) {
                __half2 p0 = __floats2half2_rn(acc[mf][nf][0], acc[mf][nf][1]);
                __half2 p1 = __floats2half2_rn(acc[mf][nf][2], acc[mf][nf][3]);
                if (row < n)
                    *(uint32_t*)&g_xlh[(size_t)row * CH + col] = *(uint32_t*)&p0;
                if (row + 8 < n)
                    *(uint32_t*)&g_xlh[(size_t)(row + 8) * CH + col] = *(uint32_t*)&p1;
            } else {
                if (row < n)
                    *(float2*)&g_xr[(size_t)row * CH + col] =
                        make_float2(acc[mf][nf][0], acc[mf][nf][1]);
                if (row + 8 < n)
                    *(float2*)&g_xr[(size_t)(row + 8) * CH + col] =
                        make_float2(acc[mf][nf][2], acc[mf][nf][3]);
            }
        }
    }
}

// ---------------- degree histogram (int4 edges; self-loops pre-seeded) -----------
__global__ void hist_k(const int* __restrict__ ei32, int E, int n) {
    int sh = g_shift;
    int tid = blockIdx.x * blockDim.x + threadIdx.x;
    int stride = gridDim.x * blockDim.x;
    if (sh == 1) {
        const int4* pd = (const int4*)(ei32 + ((size_t)E << 1));
        int nq = E >> 1;
        for (int i = tid; i < nq; i += stride) {
            int4 v = pd[i];
            if (v.x >= 0 && v.x < n) atomicAdd(&g_deg[v.x], 1);
            if (v.z >= 0 && v.z < n) atomicAdd(&g_deg[v.z], 1);
        }
        for (int i = (nq << 1) + tid; i < E; i += stride) {
            int d = ei32[(size_t)(E + i) << 1];
            if (d >= 0 && d < n) atomicAdd(&g_deg[d], 1);
        }
    } else {
        const int4* pd = (const int4*)(ei32 + E);
        int nq = E >> 2;
        for (int i = tid; i < nq; i += stride) {
            int4 v = pd[i];
            if (v.x >= 0 && v.x < n) atomicAdd(&g_deg[v.x], 1);
            if (v.y >= 0 && v.y < n) atomicAdd(&g_deg[v.y], 1);
            if (v.z >= 0 && v.z < n) atomicAdd(&g_deg[v.z], 1);
            if (v.w >= 0 && v.w < n) atomicAdd(&g_deg[v.w], 1);
        }
        for (int i = (nq << 2) + tid; i < E; i += stride) {
            int d = ei32[E + i];
            if (d >= 0 && d < n) atomicAdd(&g_deg[d], 1);
        }
    }
}

// ---------------- 2-phase exclusive scan (1024-wide blocks) ----------------------
__global__ void scan_a(int n) {
    __shared__ int s[1024];
    int b = blockIdx.x, t = threadIdx.x, i = b * 1024 + t;
    s[t] = (i < n) ? g_deg[i] : 0;
    __syncthreads();
    #pragma unroll
    for (int d = 1; d < 1024; d <<= 1) {
        int v = (t >= d) ? s[t - d] : 0;
        __syncthreads();
        s[t] += v;
        __syncthreads();
    }
    if (i < n) g_offs[i] = s[t];
    if (t == 1023) g_part[b] = s[1023];
}
// per-block prefix over <=64 partials; writes g_offs AND cursor g_cur = exclusive
__global__ void scan_c(int n) {
    __shared__ int prefix;
    int b = blockIdx.x, t = threadIdx.x;
    if (t < 32) {
        int s = 0;
        for (int i = t; i < b; i += 32) s += g_part[i];
        #pragma unroll
        for (int o = 16; o; o >>= 1) s += __shfl_xor_sync(0xFFFFFFFFu, s, o);
        if (t == 0) prefix = s;
    }
    __syncthreads();
    int i = b * 1024 + t;
    if (i >= n) return;
    int incl = g_offs[i] + prefix;
    int exc = incl - g_deg[i];
    g_offs[i] = exc;
    g_cur[i] = exc;
    if (i == n - 1) g_offs[n] = incl;
}

// ---------------- scatter: cursor carries absolute position ----------------------
__global__ void scatter_k(const int* __restrict__ ei32, int E, int n) {
    int sh = g_shift;
    int tot = E + n;
    for (int i = blockIdx.x * blockDim.x + threadIdx.x; i < tot;
         i += gridDim.x * blockDim.x) {
        int s, d;
        if (i < E) { s = ei32[(size_t)i << sh]; d = ei32[(size_t)(E + i) << sh]; }
        else       { s = d = i - E; }
        if (d < 0 || d >= n) continue;
        int pos = atomicAdd(&g_cur[d], 1);
        g_src[pos] = s;
    }
}

// ---------------- per-edge helper (half2 score path; round-12 known-good) --------
__device__ __forceinline__ void edge_acc(uint2 u, __half2 rs01, __half2 rs23,
                                         __half2 av01, __half2 av23, __half2 slope,
                                         float& a0, float& a1, float& a2, float& a3,
                                         float& den) {
    __half2 x01 = *(__half2*)&u.x;
    __half2 x23 = *(__half2*)&u.y;
    __half2 v01 = __hadd2(x01, rs01);
    __half2 v23 = __hadd2(x23, rs23);
    v01 = __hmax2(v01, __hmul2(v01, slope));
    v23 = __hmax2(v23, __hmul2(v23, slope));
    __half2 d2 = __hfma2(v01, av01, __hmul2(v23, av23));
    float sc = __half2float(__hadd(__low2half(d2), __high2half(d2)));
    sc += __shfl_xor_sync(0xFFFFFFFFu, sc, 1);
    sc += __shfl_xor_sync(0xFFFFFFFFu, sc, 2);
    sc += __shfl_xor_sync(0xFFFFFFFFu, sc, 4);
    float e = __expf(sc);
    den += e;
    float2 f01 = __half22float2(x01);
    float2 f23 = __half22float2(x23);
    a0 = fmaf(e, f01.x, a0); a1 = fmaf(e, f01.y, a1);
    a2 = fmaf(e, f23.x, a2); a3 = fmaf(e, f23.y, a3);
}

// ---------------- fused softmax-attention aggregation + BN stats -----------------
__global__ void agg_k(const float* __restrict__ att, const float* __restrict__ bias,
                      const float* __restrict__ bl, const float* __restrict__ br, int n) {
    __shared__ float ss[128], qq[128];
    int t = threadIdx.x;
    if (t < 128) { ss[t] = 0.f; qq[t] = 0.f; }
    __syncthreads();

    int w = (blockIdx.x * blockDim.x + t) >> 5;
    int lane = t & 31;

    if (w < n) {
        int beg = g_offs[w], end = g_offs[w + 1];
        float4 r   = *(const float4*)&g_xr[(size_t)w * CH + lane * 4];
        float4 blv = *(const float4*)&bl[lane * 4];
        float4 brv = *(const float4*)&br[lane * 4];
        float4 av  = *(const float4*)&att[lane * 4];
        __half2 rs01 = __floats2half2_rn(r.x + blv.x + brv.x, r.y + blv.y + brv.y);
        __half2 rs23 = __floats2half2_rn(r.z + blv.z + brv.z, r.w + blv.w + brv.w);
        __half2 av01 = __floats2half2_rn(av.x, av.y);
        __half2 av23 = __floats2half2_rn(av.z, av.w);
        const __half2 slope = __float2half2_rn(NEG_SLOPE);

        float a0 = 0.f, a1 = 0.f, a2 = 0.f, a3 = 0.f, den = 0.f;
        int p = beg;
        for (; p + 4 <= end; p += 4) {
            int s0 = g_src[p], s1 = g_src[p + 1], s2 = g_src[p + 2], s3 = g_src[p + 3];
            uint2 u0 = *(const uint2*)&g_xlh[(size_t)s0 * CH + lane * 4];
            uint2 u1 = *(const uint2*)&g_xlh[(size_t)s1 * CH + lane * 4];
            uint2 u2 = *(const uint2*)&g_xlh[(size_t)s2 * CH + lane * 4];
            uint2 u3 = *(const uint2*)&g_xlh[(size_t)s3 * CH + lane * 4];
            edge_acc(u0, rs01, rs23, av01, av23, slope, a0, a1, a2, a3, den);
            edge_acc(u1, rs01, rs23, av01, av23, slope, a0, a1, a2, a3, den);
            edge_acc(u2, rs01, rs23, av01, av23, slope, a0, a1, a2, a3, den);
            edge_acc(u3, rs01, rs23, av01, av23, slope, a0, a1, a2, a3, den);
        }
        for (; p < end; p++) {
            uint2 u0 = *(const uint2*)&g_xlh[(size_t)g_src[p] * CH + lane * 4];
            edge_acc(u0, rs01, rs23, av01, av23, slope, a0, a1, a2, a3, den);
        }

        float inv = 1.f / den;
        float4 b4 = *(const float4*)&bias[lane * 4];
        float4 o;
        o.x = fmaf(a0, inv, b4.x + blv.x);
        o.y = fmaf(a1, inv, b4.y + blv.y);
        o.z = fmaf(a2, inv, b4.z + blv.z);
        o.w = fmaf(a3, inv, b4.w + blv.w);
        *(float4*)&g_pre[(size_t)w * CH + lane * 4] = o;

        int c = lane * 4;
        atomicAdd(&ss[c + 0], o.x); atomicAdd(&qq[c + 0], o.x * o.x);
        atomicAdd(&ss[c + 1], o.y); atomicAdd(&qq[c + 1], o.y * o.y);
        atomicAdd(&ss[c + 2], o.z); atomicAdd(&qq[c + 2], o.z * o.z);
        atomicAdd(&ss[c + 3], o.w); atomicAdd(&qq[c + 3], o.w * o.w);
    }
    __syncthreads();
    if (t < 128) {
        atomicAdd(&g_sum[t], ss[t]);
        atomicAdd(&g_sumsq[t], qq[t]);
    }
}

// ---------------- final: BN + residual + ELU (float4) ----------------------------
__global__ void final_k(const float* __restrict__ x,
                        const float* __restrict__ gamma,
                        const float* __restrict__ beta,
                        float* __restrict__ out, int n) {
    int i = blockIdx.x * blockDim.x + threadIdx.x;   // float4 index
    if (i >= n * 32) return;
    int c4 = i & 31;
    float invn = 1.f / (float)n;
    float4 p = ((const float4*)g_pre)[i];
    float4 xv = ((const float4*)x)[i];
    float4 gm = ((const float4*)gamma)[c4];
    float4 bt = ((const float4*)beta)[c4];
    float4 sm4 = ((const float4*)g_sum)[c4];
    float4 sq4 = ((const float4*)g_sumsq)[c4];
    float4 o;
    {
        float mu = sm4.x * invn, var = sq4.x * invn - mu * mu;
        float y = (p.x - mu) * rsqrtf(var + BN_EPS) * gm.x + bt.x + xv.x;
        o.x = (y > 0.f) ? y : (__expf(y) - 1.f);
    }
    {
        float mu = sm4.y * invn, var = sq4.y * invn - mu * mu;
        float y = (p.y - mu) * rsqrtf(var + BN_EPS) * gm.y + bt.y + xv.y;
        o.y = (y > 0.f) ? y : (__expf(y) - 1.f);
    }
    {
        float mu = sm4.z * invn, var = sq4.z * invn - mu * mu;
        float y = (p.z - mu) * rsqrtf(var + BN_EPS) * gm.z + bt.z + xv.z;
        o.z = (y > 0.f) ? y : (__expf(y) - 1.f);
    }
    {
        float mu = sm4.w * invn, var = sq4.w * invn - mu * mu;
        float y = (p.w - mu) * rsqrtf(var + BN_EPS) * gm.w + bt.w + xv.w;
        o.w = (y > 0.f) ? y : (__expf(y) - 1.f);
    }
    ((float4*)out)[i] = o;
}

// ---------------- launch ----------------------------------------------------------
extern "C" void kernel_launch(void* const* d_in, const int* in_sizes, int n_in,
                              void* d_out, int out_size) {
    const float* x     = (const float*)d_in[0];
    const int*   ei32  = (const int*)d_in[1];
    const float* Wl    = (const float*)d_in[2];
    const float* bl    = (const float*)d_in[3];
    const float* Wr    = (const float*)d_in[4];
    const float* br    = (const float*)d_in[5];
    const float* att   = (const float*)d_in[6];
    const float* bias  = (const float*)d_in[7];
    const float* gamma = (const float*)d_in[8];
    const float* beta  = (const float*)d_in[9];
    float*       out   = (float*)d_out;

    int n = in_sizes[0] / CH;          // 50000
    int E = in_sizes[1] / 2;           // 800000
    int nb = (n + 255) / 256;
    int nb2 = (n + 1023) / 1024;       // 49

    const int SMEM_GEMM = 2 * 64 * PADK * (int)sizeof(__nv_bfloat16);  // 34816
    cudaFuncSetAttribute(gemm_mma_k, cudaFuncAttributeMaxDynamicSharedMemorySize, SMEM_GEMM);

    cudaStream_t s1;
    cudaStreamCreateWithFlags(&s1, cudaStreamNonBlocking);
    cudaEvent_t evFork, evJoin;
    cudaEventCreateWithFlags(&evFork, cudaEventDisableTiming);
    cudaEventCreateWithFlags(&evJoin, cudaEventDisableTiming);

    const int T = 256;
    init_k<<<nb, 256>>>(ei32);
    cudaEventRecord(evFork, 0);
    cudaStreamWaitEvent(s1, evFork, 0);

    // branch B (stream s1): CSR build
    hist_k<<<888, T, 0, s1>>>(ei32, E, n);
    scan_a<<<nb2, 1024, 0, s1>>>(n);
    scan_c<<<nb2, 1024, 0, s1>>>(n);
    scatter_k<<<1184, T, 0, s1>>>(ei32, E, n);
    cudaEventRecord(evJoin, s1);

    // branch A (default stream): GEMM
    pack_w_k<<<32, 256>>>(Wl, Wr);
    dim3 gg((n + 63) / 64, 2);
    gemm_mma_k<<<gg, 256, SMEM_GEMM>>>(x, n);

    cudaStreamWaitEvent(0, evJoin, 0);
    agg_k<<<((size_t)n * 32 + T - 1) / T, T>>>(att, bias, bl, br, n);
    final_k<<<(n * 32 + T - 1) / T, T>>>(x, gamma, beta, out, n);

    cudaEventDestroy(evFork);
    cudaEventDestroy(evJoin);
    cudaStreamDestroy(s1);
}

// round 17
// speedup vs baseline: 1.0933x; 1.0933x over previous
#include <cuda_runtime.h>
#include <cuda_bf16.h>
#include <cuda_fp16.h>
#include <math.h>
#include <stdint.h>

#define N_NODES 50000
#define E_EDGES 800000
#define ETOT (E_EDGES + N_NODES)
#define CH 128
#define NEG_SLOPE 0.2f
#define BN_EPS 1e-5f
#define PADK 136   // bf16 per smem row (272B) -> conflict-free ldmatrix phases

// ---------------- scratch (static device globals; no allocations) -------------
__device__ __align__(16) __half g_xlh[(size_t)N_NODES * CH];   // fp16 gather payload
__device__ __align__(16) float g_xr[(size_t)N_NODES * CH];
__device__ __align__(16) float g_pre[(size_t)N_NODES * CH];
// fragment-major packed weights: [group g=nc/8 (32)][ks (8)][lane (32)] -> uint2
__device__ __align__(16) uint2 g_wph[32 * 8 * 32];
__device__ __align__(16) uint2 g_wpl[32 * 8 * 32];
__device__ int   g_deg[N_NODES];
__device__ int   g_cur[N_NODES];      // cursor; scan_c initializes to exclusive offset
__device__ int   g_offs[N_NODES + 1];
__device__ int   g_src[ETOT];
__device__ int   g_part[256];
__device__ float g_sum[CH];
__device__ float g_sumsq[CH];
__device__ int   g_shift;   // 0: edge_index int32; 1: int64 (read low word)

// ---------------- init (+ dtype detect in block 0) ------------------------------
__global__ void init_k(const int* __restrict__ ei32) {
    int i = blockIdx.x * blockDim.x + threadIdx.x;
    if (i < N_NODES) g_deg[i] = 0;
    if (i < CH) { g_sum[i] = 0.f; g_sumsq[i] = 0.f; }
    if (blockIdx.x == 0) {
        __shared__ int nz;
        if (threadIdx.x == 0) nz = 0;
        __syncthreads();
        if (ei32[2 * threadIdx.x + 1] != 0) atomicOr(&nz, 1);
        __syncthreads();
        if (threadIdx.x == 0) g_shift = nz ? 0 : 1;
    }
}

// ---------------- pack W into B-fragment-major hi/lo layout ----------------------
__global__ void pack_w_k(const float* __restrict__ Wl, const float* __restrict__ Wr) {
    int idx = blockIdx.x * blockDim.x + threadIdx.x;
    if (idx >= 8192) return;
    int lane = idx & 31, ks = (idx >> 5) & 7, g = idx >> 8;
    int nc = g * 8 + (lane >> 2);
    int k0 = ks * 16 + (lane & 3) * 2;
    const float* W = (nc < 128) ? (Wl + nc) : (Wr + nc - 128);
    float w0 = W[(size_t)k0 * 128];
    float w1 = W[(size_t)(k0 + 1) * 128];
    float w2 = W[(size_t)(k0 + 8) * 128];
    float w3 = W[(size_t)(k0 + 9) * 128];
    __nv_bfloat16 h0 = __float2bfloat16(w0), h1 = __float2bfloat16(w1);
    __nv_bfloat16 h2 = __float2bfloat16(w2), h3 = __float2bfloat16(w3);
    __nv_bfloat162 ph0 = __halves2bfloat162(h0, h1), ph1 = __halves2bfloat162(h2, h3);
    __nv_bfloat162 pl0 = __halves2bfloat162(__float2bfloat16(w0 - __bfloat162float(h0)),
                                            __float2bfloat16(w1 - __bfloat162float(h1)));
    __nv_bfloat162 pl1 = __halves2bfloat162(__float2bfloat16(w2 - __bfloat162float(h2)),
                                            __float2bfloat16(w3 - __bfloat162float(h3)));
    g_wph[idx] = make_uint2(*(uint32_t*)&ph0, *(uint32_t*)&ph1);
    g_wpl[idx] = make_uint2(*(uint32_t*)&pl0, *(uint32_t*)&pl1);
}

// ---------------- mma / ldmatrix wrappers ----------------------------------------
__device__ __forceinline__ void mma16816(float* c, const uint32_t* a, const uint32_t* b) {
    asm volatile(
        "mma.sync.aligned.m16n8k16.row.col.f32.bf16.bf16.f32 "
        "{%0,%1,%2,%3}, {%4,%5,%6,%7}, {%8,%9}, {%0,%1,%2,%3};"
        : "+f"(c[0]), "+f"(c[1]), "+f"(c[2]), "+f"(c[3])
        : "r"(a[0]), "r"(a[1]), "r"(a[2]), "r"(a[3]), "r"(b[0]), "r"(b[1]));
}
__device__ __forceinline__ uint32_t smem_u32(const void* p) {
    uint32_t a;
    asm("{ .reg .u64 t; cvta.to.shared.u64 t, %1; cvt.u32.u64 %0, t; }" : "=r"(a) : "l"(p));
    return a;
}
#define LDMX4(r0, r1, r2, r3, a) \
    asm volatile("ldmatrix.sync.aligned.m8n8.x4.shared.b16 {%0,%1,%2,%3}, [%4];" \
        : "=r"(r0), "=r"(r1), "=r"(r2), "=r"(r3) : "r"(a))

// ---------------- tensor-core GEMM: A in smem (ldmatrix), B from packed gmem -----
__global__ void __launch_bounds__(256, 3) gemm_mma_k(const float* __restrict__ x, int n) {
    extern __shared__ __nv_bfloat16 sm[];
    __nv_bfloat16* sAh = sm;                     //  64 x PADK
    __nv_bfloat16* sAl = sAh + 64 * PADK;        //  64 x PADK

    int t = threadIdx.x;
    int row0 = blockIdx.x * 64;
    int by = blockIdx.y;

    for (int l = t; l < 2048; l += 256) {
        int r = l >> 5, j = l & 31;
        float4 v = make_float4(0.f, 0.f, 0.f, 0.f);
        if (row0 + r < n) v = ((const float4*)x)[(size_t)(row0 + r) * 32 + j];
        __nv_bfloat16 h0 = __float2bfloat16(v.x), h1 = __float2bfloat16(v.y);
        __nv_bfloat16 h2 = __float2bfloat16(v.z), h3 = __float2bfloat16(v.w);
        __nv_bfloat162 hA = __halves2bfloat162(h0, h1), hB = __halves2bfloat162(h2, h3);
        __nv_bfloat162 lA = __halves2bfloat162(__float2bfloat16(v.x - __bfloat162float(h0)),
                                               __float2bfloat16(v.y - __bfloat162float(h1)));
        __nv_bfloat162 lB = __halves2bfloat162(__float2bfloat16(v.z - __bfloat162float(h2)),
                                               __float2bfloat16(v.w - __bfloat162float(h3)));
        *(uint2*)&sAh[r * PADK + j * 4] = make_uint2(*(uint32_t*)&hA, *(uint32_t*)&hB);
        *(uint2*)&sAl[r * PADK + j * 4] = make_uint2(*(uint32_t*)&lA, *(uint32_t*)&lB);
    }
    __syncthreads();

    int warp = t >> 5, lane = t & 31;
    int rg = warp >> 2, cg = warp & 3;
    int lr = lane >> 2, lk = (lane & 3) * 2;

    uint32_t aRow = (uint32_t)(rg * 32 + (lane & 15));
    uint32_t aKof = (uint32_t)((lane >> 4) << 3);
    uint32_t aOff = (aRow * PADK + aKof) * 2;
    uint32_t ah_base = smem_u32(sAh) + aOff;
    uint32_t al_base = smem_u32(sAl) + aOff;
    const uint32_t MF_STEP = 16 * PADK * 2;

    int bbase = (by * 16 + cg * 4) * 256 + lane;

    float acc[2][4][4];
    #pragma unroll
    for (int mf = 0; mf < 2; mf++)
        #pragma unroll
        for (int nf = 0; nf < 4; nf++)
            #pragma unroll
            for (int q = 0; q < 4; q++) acc[mf][nf][q] = 0.f;

    #pragma unroll
    for (int ks = 0; ks < 8; ks++) {
        uint32_t ko = (uint32_t)ks * 32;
        uint32_t ah[2][4], al[2][4];
        LDMX4(ah[0][0], ah[0][1], ah[0][2], ah[0][3], ah_base + ko);
        LDMX4(ah[1][0], ah[1][1], ah[1][2], ah[1][3], ah_base + MF_STEP + ko);
        LDMX4(al[0][0], al[0][1], al[0][2], al[0][3], al_base + ko);
        LDMX4(al[1][0], al[1][1], al[1][2], al[1][3], al_base + MF_STEP + ko);
        #pragma unroll
        for (int nf = 0; nf < 4; nf++) {
            uint2 bh = g_wph[bbase + nf * 256 + ks * 32];
            uint2 bl = g_wpl[bbase + nf * 256 + ks * 32];
            uint32_t bhv[2] = {bh.x, bh.y};
            uint32_t blv[2] = {bl.x, bl.y};
            #pragma unroll
            for (int mf = 0; mf < 2; mf++) {
                mma16816(acc[mf][nf], ah[mf], bhv);
                mma16816(acc[mf][nf], ah[mf], blv);
                mma16816(acc[mf][nf], al[mf], bhv);
            }
        }
    }

    #pragma unroll
    for (int mf = 0; mf < 2; mf++) {
        int row = row0 + rg * 32 + mf * 16 + lr;
        #pragma unroll
        for (int nf = 0; nf < 4; nf++) {
            int col = cg * 32 + nf * 8 + lk;
            if (by == 0) {
                __half2 p0 = __floats2half2_rn(acc[mf][nf][0], acc[mf][nf][1]);
                __half2 p1 = __floats2half2_rn(acc[mf][nf][2], acc[mf][nf][3]);
                if (row < n)
                    *(uint32_t*)&g_xlh[(size_t)row * CH + col] = *(uint32_t*)&p0;
                if (row + 8 < n)
                    *(uint32_t*)&g_xlh[(size_t)(row + 8) * CH + col] = *(uint32_t*)&p1;
            } else {
                if (row < n)
                    *(float2*)&g_xr[(size_t)row * CH + col] =
                        make_float2(acc[mf][nf][0], acc[mf][nf][1]);
                if (row + 8 < n)
                    *(float2*)&g_xr[(size_t)(row + 8) * CH + col] =
                        make_float2(acc[mf][nf][2], acc[mf][nf][3]);
            }
        }
    }
}

// ---------------- degree histogram (grid-stride; round-12 known-good) ------------
__global__ void hist_k(const int* __restrict__ ei32, int E, int n) {
    int sh = g_shift;
    int tot = E + n;
    for (int i = blockIdx.x * blockDim.x + threadIdx.x; i < tot;
         i += gridDim.x * blockDim.x) {
        int d = (i < E) ? ei32[(size_t)(E + i) << sh] : (i - E);
        if (d >= 0 && d < n) atomicAdd(&g_deg[d], 1);
    }
}

// ---------------- 2-phase exclusive scan (round-12 known-good) -------------------
__global__ void scan_a(int n) {
    __shared__ int s[256];
    int b = blockIdx.x, t = threadIdx.x, i = b * 256 + t;
    s[t] = (i < n) ? g_deg[i] : 0;
    __syncthreads();
    #pragma unroll
    for (int d = 1; d < 256; d <<= 1) {
        int v = (t >= d) ? s[t - d] : 0;
        __syncthreads();
        s[t] += v;
        __syncthreads();
    }
    if (i < n) g_offs[i] = s[t];
    if (t == 255) g_part[b] = s[255];
}
// per-block prefix; ALSO initializes cursor g_cur = exclusive offset
__global__ void scan_c(int n) {
    __shared__ int prefix;
    int b = blockIdx.x, t = threadIdx.x;
    if (t < 32) {
        int s = 0;
        for (int i = t; i < b; i += 32) s += g_part[i];
        #pragma unroll
        for (int o = 16; o; o >>= 1) s += __shfl_xor_sync(0xFFFFFFFFu, s, o);
        if (t == 0) prefix = s;
    }
    __syncthreads();
    int i = b * 256 + t;
    if (i >= n) return;
    int incl = g_offs[i] + prefix;
    int exc = incl - g_deg[i];
    g_offs[i] = exc;
    g_cur[i] = exc;
    if (i == n - 1) g_offs[n] = incl;
}

// ---------------- scatter: cursor carries absolute position ----------------------
__global__ void scatter_k(const int* __restrict__ ei32, int E, int n) {
    int sh = g_shift;
    int tot = E + n;
    for (int i = blockIdx.x * blockDim.x + threadIdx.x; i < tot;
         i += gridDim.x * blockDim.x) {
        int s, d;
        if (i < E) { s = ei32[(size_t)i << sh]; d = ei32[(size_t)(E + i) << sh]; }
        else       { s = d = i - E; }
        if (d < 0 || d >= n) continue;
        int pos = atomicAdd(&g_cur[d], 1);
        g_src[pos] = s;
    }
}

// ---------------- per-edge helper (half2 score path; round-12 known-good) --------
__device__ __forceinline__ void edge_acc(uint2 u, __half2 rs01, __half2 rs23,
                                         __half2 av01, __half2 av23, __half2 slope,
                                         float& a0, float& a1, float& a2, float& a3,
                                         float& den) {
    __half2 x01 = *(__half2*)&u.x;
    __half2 x23 = *(__half2*)&u.y;
    __half2 v01 = __hadd2(x01, rs01);
    __half2 v23 = __hadd2(x23, rs23);
    v01 = __hmax2(v01, __hmul2(v01, slope));
    v23 = __hmax2(v23, __hmul2(v23, slope));
    __half2 d2 = __hfma2(v01, av01, __hmul2(v23, av23));
    float sc = __half2float(__hadd(__low2half(d2), __high2half(d2)));
    sc += __shfl_xor_sync(0xFFFFFFFFu, sc, 1);
    sc += __shfl_xor_sync(0xFFFFFFFFu, sc, 2);
    sc += __shfl_xor_sync(0xFFFFFFFFu, sc, 4);
    float e = __expf(sc);
    den += e;
    float2 f01 = __half22float2(x01);
    float2 f23 = __half22float2(x23);
    a0 = fmaf(e, f01.x, a0); a1 = fmaf(e, f01.y, a1);
    a2 = fmaf(e, f23.x, a2); a3 = fmaf(e, f23.y, a3);
}

// ---------------- fused softmax-attention aggregation + BN stats -----------------
__global__ void agg_k(const float* __restrict__ att, const float* __restrict__ bias,
                      const float* __restrict__ bl, const float* __restrict__ br, int n) {
    __shared__ float ss[128], qq[128];
    int t = threadIdx.x;
    if (t < 128) { ss[t] = 0.f; qq[t] = 0.f; }
    __syncthreads();

    int w = (blockIdx.x * blockDim.x + t) >> 5;
    int lane = t & 31;

    if (w < n) {
        int beg = g_offs[w], end = g_offs[w + 1];
        float4 r   = *(const float4*)&g_xr[(size_t)w * CH + lane * 4];
        float4 blv = *(const float4*)&bl[lane * 4];
        float4 brv = *(const float4*)&br[lane * 4];
        float4 av  = *(const float4*)&att[lane * 4];
        __half2 rs01 = __floats2half2_rn(r.x + blv.x + brv.x, r.y + blv.y + brv.y);
        __half2 rs23 = __floats2half2_rn(r.z + blv.z + brv.z, r.w + blv.w + brv.w);
        __half2 av01 = __floats2half2_rn(av.x, av.y);
        __half2 av23 = __floats2half2_rn(av.z, av.w);
        const __half2 slope = __float2half2_rn(NEG_SLOPE);

        float a0 = 0.f, a1 = 0.f, a2 = 0.f, a3 = 0.f, den = 0.f;
        int p = beg;
        for (; p + 4 <= end; p += 4) {
            int s0 = g_src[p], s1 = g_src[p + 1], s2 = g_src[p + 2], s3 = g_src[p + 3];
            uint2 u0 = *(const uint2*)&g_xlh[(size_t)s0 * CH + lane * 4];
            uint2 u1 = *(const uint2*)&g_xlh[(size_t)s1 * CH + lane * 4];
            uint2 u2 = *(const uint2*)&g_xlh[(size_t)s2 * CH + lane * 4];
            uint2 u3 = *(const uint2*)&g_xlh[(size_t)s3 * CH + lane * 4];
            edge_acc(u0, rs01, rs23, av01, av23, slope, a0, a1, a2, a3, den);
            edge_acc(u1, rs01, rs23, av01, av23, slope, a0, a1, a2, a3, den);
            edge_acc(u2, rs01, rs23, av01, av23, slope, a0, a1, a2, a3, den);
            edge_acc(u3, rs01, rs23, av01, av23, slope, a0, a1, a2, a3, den);
        }
        for (; p < end; p++) {
            uint2 u0 = *(const uint2*)&g_xlh[(size_t)g_src[p] * CH + lane * 4];
            edge_acc(u0, rs01, rs23, av01, av23, slope, a0, a1, a2, a3, den);
        }

        float inv = 1.f / den;
        float4 b4 = *(const float4*)&bias[lane * 4];
        float4 o;
        o.x = fmaf(a0, inv, b4.x + blv.x);
        o.y = fmaf(a1, inv, b4.y + blv.y);
        o.z = fmaf(a2, inv, b4.z + blv.z);
        o.w = fmaf(a3, inv, b4.w + blv.w);
        *(float4*)&g_pre[(size_t)w * CH + lane * 4] = o;

        int c = lane * 4;
        atomicAdd(&ss[c + 0], o.x); atomicAdd(&qq[c + 0], o.x * o.x);
        atomicAdd(&ss[c + 1], o.y); atomicAdd(&qq[c + 1], o.y * o.y);
        atomicAdd(&ss[c + 2], o.z); atomicAdd(&qq[c + 2], o.z * o.z);
        atomicAdd(&ss[c + 3], o.w); atomicAdd(&qq[c + 3], o.w * o.w);
    }
    __syncthreads();
    if (t < 128) {
        atomicAdd(&g_sum[t], ss[t]);
        atomicAdd(&g_sumsq[t], qq[t]);
    }
}

// ---------------- final: BN + residual + ELU (float4) ----------------------------
__global__ void final_k(const float* __restrict__ x,
                        const float* __restrict__ gamma,
                        const float* __restrict__ beta,
                        float* __restrict__ out, int n) {
    int i = blockIdx.x * blockDim.x + threadIdx.x;   // float4 index
    if (i >= n * 32) return;
    int c4 = i & 31;
    float invn = 1.f / (float)n;
    float4 p = ((const float4*)g_pre)[i];
    float4 xv = ((const float4*)x)[i];
    float4 gm = ((const float4*)gamma)[c4];
    float4 bt = ((const float4*)beta)[c4];
    float4 sm4 = ((const float4*)g_sum)[c4];
    float4 sq4 = ((const float4*)g_sumsq)[c4];
    float4 o;
    {
        float mu = sm4.x * invn, var = sq4.x * invn - mu * mu;
        float y = (p.x - mu) * rsqrtf(var + BN_EPS) * gm.x + bt.x + xv.x;
        o.x = (y > 0.f) ? y : (__expf(y) - 1.f);
    }
    {
        float mu = sm4.y * invn, var = sq4.y * invn - mu * mu;
        float y = (p.y - mu) * rsqrtf(var + BN_EPS) * gm.y + bt.y + xv.y;
        o.y = (y > 0.f) ? y : (__expf(y) - 1.f);
    }
    {
        float mu = sm4.z * invn, var = sq4.z * invn - mu * mu;
        float y = (p.z - mu) * rsqrtf(var + BN_EPS) * gm.z + bt.z + xv.z;
        o.z = (y > 0.f) ? y : (__expf(y) - 1.f);
    }
    {
        float mu = sm4.w * invn, var = sq4.w * invn - mu * mu;
        float y = (p.w - mu) * rsqrtf(var + BN_EPS) * gm.w + bt.w + xv.w;
        o.w = (y > 0.f) ? y : (__expf(y) - 1.f);
    }
    ((float4*)out)[i] = o;
}

// ---------------- launch ----------------------------------------------------------
extern "C" void kernel_launch(void* const* d_in, const int* in_sizes, int n_in,
                              void* d_out, int out_size) {
    const float* x     = (const float*)d_in[0];
    const int*   ei32  = (const int*)d_in[1];
    const float* Wl    = (const float*)d_in[2];
    const float* bl    = (const float*)d_in[3];
    const float* Wr    = (const float*)d_in[4];
    const float* br    = (const float*)d_in[5];
    const float* att   = (const float*)d_in[6];
    const float* bias  = (const float*)d_in[7];
    const float* gamma = (const float*)d_in[8];
    const float* beta  = (const float*)d_in[9];
    float*       out   = (float*)d_out;

    int n = in_sizes[0] / CH;          // 50000
    int E = in_sizes[1] / 2;           // 800000
    int nb = (n + 255) / 256;

    const int SMEM_GEMM = 2 * 64 * PADK * (int)sizeof(__nv_bfloat16);  // 34816
    cudaFuncSetAttribute(gemm_mma_k, cudaFuncAttributeMaxDynamicSharedMemorySize, SMEM_GEMM);

    cudaStream_t s1;
    cudaStreamCreateWithFlags(&s1, cudaStreamNonBlocking);
    cudaEvent_t evFork, evJoin;
    cudaEventCreateWithFlags(&evFork, cudaEventDisableTiming);
    cudaEventCreateWithFlags(&evJoin, cudaEventDisableTiming);

    const int T = 256;
    init_k<<<nb, 256>>>(ei32);
    cudaEventRecord(evFork, 0);
    cudaStreamWaitEvent(s1, evFork, 0);

    // branch B (stream s1): CSR build
    hist_k<<<1184, T, 0, s1>>>(ei32, E, n);
    scan_a<<<nb, 256, 0, s1>>>(n);
    scan_c<<<nb, 256, 0, s1>>>(n);
    scatter_k<<<1184, T, 0, s1>>>(ei32, E, n);
    cudaEventRecord(evJoin, s1);

    // branch A (default stream): GEMM
    pack_w_k<<<32, 256>>>(Wl, Wr);
    dim3 gg((n + 63) / 64, 2);
    gemm_mma_k<<<gg, 256, SMEM_GEMM>>>(x, n);

    cudaStreamWaitEvent(0, evJoin, 0);
    agg_k<<<((size_t)n * 32 + T - 1) / T, T>>>(att, bias, bl, br, n);
    final_k<<<(n * 32 + T - 1) / T, T>>>(x, gamma, beta, out, n);

    cudaEventDestroy(evFork);
    cudaEventDestroy(evJoin);
    cudaStreamDestroy(s1);
}